// round 14
// baseline (speedup 1.0000x reference)
#include <cuda_runtime.h>
#include <math.h>

#define NTOK 32768
#define NH 8
#define HD 24
#define HDIM 28
#define NSEG 48
#define CHUNK 4096

typedef unsigned long long ull;

#define FMA_F32X2(d, a, b, c) \
    asm("fma.rn.f32x2 %0, %1, %2, %3;" : "=l"(d) : "l"(a), "l"(b), "l"(c))
#define PACK_F32X2(out, lo, hi) \
    asm("mov.b64 %0, {%1, %2};" : "=l"(out) : "r"(lo), "r"(hi))
#define UNPACK_F32X2(lo, hi, in) \
    asm("mov.b64 {%0, %1}, %2;" : "=r"(lo), "=r"(hi) : "l"(in))

// ---------- scratch ----------
static __device__ float g_qkv[(size_t)NTOK * 576];
static __device__ float g_qhat[(size_t)NH * NTOK * HDIM];
static __device__ float g_khat[(size_t)NH * NTOK * HDIM];
static __device__ ull   g_keys[(size_t)NSEG * NTOK];
static __device__ float g_o[(size_t)24 * NTOK * HD];
static __device__ float g_z[(size_t)24 * NTOK];

__device__ __forceinline__ unsigned ford(float f) {
    unsigned u = __float_as_uint(f);
    return (u & 0x80000000u) ? ~u : (u | 0x80000000u);
}

__device__ __forceinline__ void cswap(ull& a, ull& b, bool asc) {
    if ((a > b) == asc) { ull t = a; a = b; b = t; }
}

__device__ __forceinline__ void tail8(ull e[8], bool asc) {
    #pragma unroll
    for (int r = 0; r < 4; r++) cswap(e[r], e[r + 4], asc);
    #pragma unroll
    for (int r = 0; r < 8; r++) if (!(r & 2)) cswap(e[r], e[r | 2], asc);
    #pragma unroll
    for (int r = 0; r < 8; r += 2) cswap(e[r], e[r + 1], asc);
}

template <int K>
__device__ __forceinline__ void reg_tail(ull e[8], int g0) {
    #pragma unroll
    for (int j = (K > 8 ? 4 : K / 2); j > 0; j >>= 1) {
        #pragma unroll
        for (int r = 0; r < 8; r++) {
            if (!(r & j)) {
                bool asc = (((g0 + r) & K) == 0);
                cswap(e[r], e[r | j], asc);
            }
        }
    }
}

__device__ __forceinline__ void spass4(ull* s, int pbase, int j, bool asc) {
    int i = ((pbase & ~(j - 1)) << 1) | (pbase & (j - 1));
    ulonglong2 a0 = *(ulonglong2*)(s + i);
    ulonglong2 a1 = *(ulonglong2*)(s + i + 2);
    ulonglong2 b0 = *(ulonglong2*)(s + i + j);
    ulonglong2 b1 = *(ulonglong2*)(s + i + j + 2);
    cswap(a0.x, b0.x, asc); cswap(a0.y, b0.y, asc);
    cswap(a1.x, b1.x, asc); cswap(a1.y, b1.y, asc);
    *(ulonglong2*)(s + i) = a0;
    *(ulonglong2*)(s + i + 2) = a1;
    *(ulonglong2*)(s + i + j) = b0;
    *(ulonglong2*)(s + i + j + 2) = b1;
}

// ---------- LayerNorm1 + QKV GEMM ----------
__global__ void __launch_bounds__(576) k_ln_qkv(
    const float* __restrict__ x, const float* __restrict__ g1, const float* __restrict__ b1,
    const float* __restrict__ Wq, const float* __restrict__ Wk, const float* __restrict__ Wv) {
    __shared__ __align__(16) float xnt[24][68];
    int base = blockIdx.x * 64;
    int tid = threadIdx.x;
    if (tid < 64) {
        int row = base + tid;
        float xv[24];
        float mu = 0.f;
        #pragma unroll
        for (int i = 0; i < 24; i++) { xv[i] = x[(size_t)row * 24 + i]; mu += xv[i]; }
        mu *= (1.f / 24.f);
        float var = 0.f;
        #pragma unroll
        for (int i = 0; i < 24; i++) { float d = xv[i] - mu; var += d * d; }
        var *= (1.f / 24.f);
        float inv = rsqrtf(var + 1e-5f);
        #pragma unroll
        for (int i = 0; i < 24; i++) xnt[i][tid] = (xv[i] - mu) * inv * g1[i] + b1[i];
    }
    __syncthreads();
    int col = tid;
    const float* W;
    int cc;
    if (col < 192)      { W = Wq; cc = col; }
    else if (col < 384) { W = Wk; cc = col - 192; }
    else                { W = Wv; cc = col - 384; }
    float w[24];
    #pragma unroll
    for (int i = 0; i < 24; i++) w[i] = W[i * 192 + cc];
    #pragma unroll 2
    for (int r4 = 0; r4 < 16; r4++) {
        float a0 = 0.f, a1 = 0.f, a2 = 0.f, a3 = 0.f;
        #pragma unroll
        for (int i = 0; i < 24; i++) {
            float4 xr = *(const float4*)&xnt[i][r4 * 4];
            a0 = fmaf(xr.x, w[i], a0);
            a1 = fmaf(xr.y, w[i], a1);
            a2 = fmaf(xr.z, w[i], a2);
            a3 = fmaf(xr.w, w[i], a3);
        }
        size_t o = (size_t)(base + r4 * 4) * 576 + col;
        g_qkv[o] = a0;
        g_qkv[o + 576] = a1;
        g_qkv[o + 1152] = a2;
        g_qkv[o + 1728] = a3;
    }
}

// ---------- build q_hat/k_hat + keys ----------
__global__ void __launch_bounds__(256) k_build(const float* __restrict__ coords,
                                               const float* __restrict__ alphas,
                                               const float* __restrict__ Wrpe) {
    __shared__ float stage[8 * 929];
    __shared__ ull ksm[48 * 32];
    __shared__ float wsm[16], wsqm[16];
    int tid = threadIdx.x;
    int n0 = blockIdx.x * 32;
    if (tid < 16) {
        int h = tid >> 1, c = tid & 1;
        float s = 0.f;
        for (int i = 0; i < 24; i++)
            for (int j = 0; j < 8; j++)
                s += Wrpe[(h * 24 + i) * 16 + c * 8 + j];
        s *= (1.f / 192.f);
        wsm[tid] = s * s;
        wsqm[tid] = sqrtf(2.f * s * s);
    }
    __syncthreads();

    int h = tid & 7, nl = tid >> 3;
    int n = n0 + nl;
    float p0 = coords[n * 3 + 1], p1 = coords[n * 3 + 2];
    float sqn = wsm[h * 2] * p0 * p0 + wsm[h * 2 + 1] * p1 * p1;
    float qp0 = wsqm[h * 2] * p0, qp1 = wsqm[h * 2 + 1] * p1;
    float qh[HDIM], kh[HDIM];
    const float* qkv = &g_qkv[(size_t)n * 576];
    const float qscale = 0.2041241452319315f;
    #pragma unroll
    for (int i = 0; i < 24; i++) { qh[i] = qkv[h * 24 + i] * qscale; kh[i] = qkv[192 + h * 24 + i]; }
    qh[24] = qp0; qh[25] = qp1; qh[26] = -sqn; qh[27] = 1.f;
    kh[24] = qp0; kh[25] = qp1; kh[26] = 1.f;  kh[27] = -sqn;

    #pragma unroll
    for (int r = 0; r < 3; r++) {
        const float* a = &alphas[(r * 8 + h) * HDIM];
        float sq = 0.f, sk = 0.f;
        #pragma unroll
        for (int i = 0; i < HDIM; i++) { sq = fmaf(qh[i], a[i], sq); sk = fmaf(kh[i], a[i], sk); }
        ksm[(r * 8 + h) * 32 + nl] = ((ull)ford(sq) << 32) | (unsigned)n;
        ksm[(24 + r * 8 + h) * 32 + nl] = ((ull)ford(sk) << 32) | (unsigned)n;
    }

    #pragma unroll
    for (int i = 0; i < HDIM; i++) stage[h * 929 + nl * 29 + i] = qh[i];
    __syncthreads();
    for (int e = tid; e < 8 * 896; e += 256) {
        int hh = e / 896, rr = e - hh * 896;
        g_qhat[(size_t)hh * NTOK * 28 + (size_t)n0 * 28 + rr] =
            stage[hh * 929 + (rr / 28) * 29 + rr % 28];
    }
    __syncthreads();
    #pragma unroll
    for (int i = 0; i < HDIM; i++) stage[h * 929 + nl * 29 + i] = kh[i];
    __syncthreads();
    for (int e = tid; e < 8 * 896; e += 256) {
        int hh = e / 896, rr = e - hh * 896;
        g_khat[(size_t)hh * NTOK * 28 + (size_t)n0 * 28 + rr] =
            stage[hh * 929 + (rr / 28) * 29 + rr % 28];
    }
    for (int e = tid; e < 48 * 32; e += 256) {
        int seg = e >> 5, nn = e & 31;
        g_keys[(size_t)seg * NTOK + n0 + nn] = ksm[e];
    }
}

// ---------- bitonic: presort ----------
__global__ void __launch_bounds__(512) k_presort() {
    __shared__ __align__(16) ull s[CHUNK];
    int seg = blockIdx.x >> 3, chunk = blockIdx.x & 7;
    size_t gb = (size_t)seg * NTOK + (size_t)chunk * CHUNK;
    int base = chunk * CHUNK;
    int t = threadIdx.x;
    int e0 = t * 8;
    int g0 = base + e0;

    ull e[8];
    #pragma unroll
    for (int r = 0; r < 8; r++) e[r] = g_keys[gb + e0 + r];
    reg_tail<2>(e, g0);
    reg_tail<4>(e, g0);
    reg_tail<8>(e, g0);
    #pragma unroll
    for (int r = 0; r < 8; r++) s[e0 + r] = e[r];
    __syncthreads();

    for (int k = 16; k <= CHUNK; k <<= 1) {
        for (int j = k >> 1; j >= 8; j >>= 1) {
            int pbase = t * 4;
            int i = ((pbase & ~(j - 1)) << 1) | (pbase & (j - 1));
            bool asc = (((base + i) & k) == 0);
            spass4(s, pbase, j, asc);
            __syncthreads();
        }
        #pragma unroll
        for (int r = 0; r < 8; r++) e[r] = s[e0 + r];
        bool asc = ((g0 & k) == 0);
        tail8(e, asc);
        if (k < CHUNK) {
            #pragma unroll
            for (int r = 0; r < 8; r++) s[e0 + r] = e[r];
            __syncthreads();
        }
    }
    #pragma unroll
    for (int r = 0; r < 8; r++) g_keys[gb + e0 + r] = e[r];
}

// ---------- fused global merge ----------
__global__ void __launch_bounds__(256) k_gmerge(int k) {
    int t = blockIdx.x * 256 + threadIdx.x;
    int seg = t >> 12;
    int g = t & 4095;
    size_t bs = (size_t)seg * NTOK;
    ull e[8];
    #pragma unroll
    for (int m = 0; m < 8; m++) e[m] = g_keys[bs + g + 4096 * m];
    #pragma unroll
    for (int j = 4; j >= 1; j >>= 1) {
        if (j * 8192 <= k) {
            #pragma unroll
            for (int m = 0; m < 8; m++) {
                if (!(m & j)) {
                    bool asc = (((m * 4096) & k) == 0);
                    cswap(e[m], e[m + j], asc);
                }
            }
        }
    }
    #pragma unroll
    for (int m = 0; m < 8; m++) g_keys[bs + g + 4096 * m] = e[m];
}

// ---------- bitonic: finish ----------
__global__ void __launch_bounds__(512) k_finish(int k) {
    __shared__ __align__(16) ull s[CHUNK];
    int seg = blockIdx.x >> 3, chunk = blockIdx.x & 7;
    size_t gb = (size_t)seg * NTOK + (size_t)chunk * CHUNK;
    int base = chunk * CHUNK;
    int t = threadIdx.x;
    int e0 = t * 8;
    #pragma unroll
    for (int u = 0; u < 2; u++) {
        int i = (t + u * 512) * 4;
        *(ulonglong2*)(s + i)     = *(const ulonglong2*)(g_keys + gb + i);
        *(ulonglong2*)(s + i + 2) = *(const ulonglong2*)(g_keys + gb + i + 2);
    }
    __syncthreads();
    bool asc = ((base & k) == 0);
    for (int j = CHUNK >> 1; j >= 8; j >>= 1) {
        spass4(s, t * 4, j, asc);
        __syncthreads();
    }
    ull e[8];
    #pragma unroll
    for (int r = 0; r < 8; r++) e[r] = s[e0 + r];
    tail8(e, asc);
    #pragma unroll
    for (int r = 0; r < 8; r++) g_keys[gb + e0 + r] = e[r];
}

// ---------- block attention v6: half-tiles 64x128, 256 thr, 4 CTAs/SM ----------
__global__ void __launch_bounds__(256, 4) k_attn() {
    __shared__ __align__(16) float SP[9208];    // 36832 B
    float* qs_t = SP;                           // [28][66]  : 0..1848
    float* ks   = SP + 1848;                    // [128][30] : 1848..5688
    float* vs   = SP + 5688;                    // [128][26] : 5688..9016
    int* qidx = (int*)(SP + 9016);              // 64
    int* kidx = (int*)(SP + 9080);              // 128
    float* pbuf = SP;                           // PV: [32][66] : 0..2112 (qs_t/ks dead)

    int tid = threadIdx.x;
    int b = blockIdx.x, h = blockIdx.y, r = blockIdx.z;
    int seg = r * 8 + h;
    int kb = b >> 1;

    if (tid < 64)
        qidx[tid] = (int)(g_keys[(size_t)seg * NTOK + b * 64 + tid] & 0xffffffffu);
    else if (tid < 192) {
        int t = tid - 64;
        kidx[t] = (int)(g_keys[(size_t)(24 + seg) * NTOK + kb * 128 + t] & 0xffffffffu);
    }
    __syncthreads();
    for (int i = tid; i < 64 * 28; i += 256) {
        int row = i / 28, kk = i - row * 28;
        qs_t[kk * 66 + row] = g_qhat[((size_t)h * NTOK + qidx[row]) * HDIM + kk];
    }
    for (int i = tid; i < 128 * 28; i += 256) {
        int row = i / 28, kk = i - row * 28;
        ks[row * 30 + kk] = g_khat[((size_t)h * NTOK + kidx[row]) * HDIM + kk];
    }
    for (int i = tid; i < 128 * 24; i += 256) {
        int row = i / 24, kk = i - row * 24;
        vs[row * 26 + kk] = g_qkv[(size_t)kidx[row] * 576 + 384 + h * 24 + kk];
    }
    __syncthreads();

    int ty = tid >> 4, tx = tid & 15;          // ty 0..15
    int R0 = ty * 4;                           // rows R0..R0+3 (of 64)
    ull acc2[2][8];                            // [rowpair u][col c]: rows (R0+2u, R0+2u+1)
    #pragma unroll
    for (int u = 0; u < 2; u++)
        #pragma unroll
        for (int c = 0; c < 8; c++) acc2[u][c] = 0ULL;

    #pragma unroll 2
    for (int kk = 0; kk < 28; kk++) {
        ull qp0 = *(const ull*)&qs_t[kk * 66 + R0];
        ull qp1 = *(const ull*)&qs_t[kk * 66 + R0 + 2];
        #pragma unroll
        for (int c = 0; c < 8; c++) {
            float kv = ks[(tx + 16 * c) * 30 + kk];
            unsigned kb2 = __float_as_uint(kv);
            ull kp;
            PACK_F32X2(kp, kb2, kb2);
            FMA_F32X2(acc2[0][c], qp0, kp, acc2[0][c]);
            FMA_F32X2(acc2[1][c], qp1, kp, acc2[1][c]);
        }
    }

    // softmax per rowpair (transient unpack)
    #pragma unroll
    for (int u = 0; u < 2; u++) {
        float vlo[8], vhi[8];
        #pragma unroll
        for (int c = 0; c < 8; c++) {
            unsigned lo, hi;
            UNPACK_F32X2(lo, hi, acc2[u][c]);
            vlo[c] = __uint_as_float(lo);
            vhi[c] = __uint_as_float(hi);
        }
        float mlo = vlo[0], mhi = vhi[0];
        #pragma unroll
        for (int c = 1; c < 8; c++) { mlo = fmaxf(mlo, vlo[c]); mhi = fmaxf(mhi, vhi[c]); }
        #pragma unroll
        for (int s = 1; s < 16; s <<= 1) {
            mlo = fmaxf(mlo, __shfl_xor_sync(0xffffffffu, mlo, s));
            mhi = fmaxf(mhi, __shfl_xor_sync(0xffffffffu, mhi, s));
        }
        float slo = 0.f, shi = 0.f;
        #pragma unroll
        for (int c = 0; c < 8; c++) {
            vlo[c] = __expf(vlo[c] - mlo); slo += vlo[c];
            vhi[c] = __expf(vhi[c] - mhi); shi += vhi[c];
        }
        #pragma unroll
        for (int s = 1; s < 16; s <<= 1) {
            slo += __shfl_xor_sync(0xffffffffu, slo, s);
            shi += __shfl_xor_sync(0xffffffffu, shi, s);
        }
        float ilo = 1.f / slo, ihi = 1.f / shi;
        #pragma unroll
        for (int c = 0; c < 8; c++) {
            unsigned lo = __float_as_uint(vlo[c] * ilo);
            unsigned hi = __float_as_uint(vhi[c] * ihi);
            PACK_F32X2(acc2[u][c], lo, hi);
        }
        if (tx == 0) {
            g_z[(size_t)seg * NTOK + qidx[R0 + 2 * u]]     = __logf(slo) + mlo;
            g_z[(size_t)seg * NTOK + qidx[R0 + 2 * u + 1]] = __logf(shi) + mhi;
        }
    }

    // PV: 4 rounds of 32 cols; thread = (rowpair s of 32, dim-group dg of 8)
    int s = tid & 31;                  // rowpair: rows 2s, 2s+1 (of 64)
    int dg = tid >> 5;                 // 0..7 → dims dg*3 .. dg*3+2
    ull oap[3];
    #pragma unroll
    for (int d = 0; d < 3; d++) oap[d] = 0ULL;

    for (int round = 0; round < 4; round++) {
        __syncthreads();
        #pragma unroll
        for (int cc2 = 0; cc2 < 2; cc2++) {
            int cc = round * 2 + cc2;
            int lc = tx + 16 * cc2;
            *(ull*)&pbuf[lc * 66 + R0]     = acc2[0][cc];
            *(ull*)&pbuf[lc * 66 + R0 + 2] = acc2[1][cc];
        }
        __syncthreads();
        #pragma unroll 4
        for (int c16 = 0; c16 < 32; c16++) {
            ull pp = *(const ull*)&pbuf[c16 * 66 + 2 * s];
            int gcol = round * 32 + c16;
            const float* vv = &vs[gcol * 26 + dg * 3];
            #pragma unroll
            for (int d = 0; d < 3; d++) {
                unsigned vb = __float_as_uint(vv[d]);
                ull vp;
                PACK_F32X2(vp, vb, vb);
                FMA_F32X2(oap[d], pp, vp, oap[d]);
            }
        }
    }
    {
        int n0 = qidx[2 * s], n1 = qidx[2 * s + 1];
        float* o0 = &g_o[((size_t)seg * NTOK + n0) * 24 + dg * 3];
        float* o1 = &g_o[((size_t)seg * NTOK + n1) * 24 + dg * 3];
        #pragma unroll
        for (int d = 0; d < 3; d++) {
            unsigned lo, hi;
            UNPACK_F32X2(lo, hi, oap[d]);
            o0[d] = __uint_as_float(lo);
            o1[d] = __uint_as_float(hi);
        }
    }
}

// ---------- combine ----------
__global__ void __launch_bounds__(512) k_combine(
    const float* __restrict__ x, const float* __restrict__ Wo, const float* __restrict__ bo,
    const float* __restrict__ g2, const float* __restrict__ b2v,
    const float* __restrict__ W1, const float* __restrict__ b1v,
    const float* __restrict__ W2, const float* __restrict__ b2f,
    float* __restrict__ out) {
    __shared__ float Wo_s[4608];
    __shared__ float outs[16][192];
    __shared__ float wsm[16][24];
    __shared__ float hsm[16][24];
    __shared__ float fsm[16][24];
    int warp = threadIdx.x >> 5, lane = threadIdx.x & 31;
    int row = blockIdx.x * 16 + warp;

    for (int i = threadIdx.x; i < 4608; i += 512) Wo_s[i] = Wo[i];
    __syncthreads();

    if (lane < 8) {
        int h = lane;
        float z0 = g_z[(size_t)h * NTOK + row];
        float z1 = g_z[(size_t)(8 + h) * NTOK + row];
        float z2 = g_z[(size_t)(16 + h) * NTOK + row];
        float m = fmaxf(z0, fmaxf(z1, z2));
        float e0 = __expf(z0 - m), e1 = __expf(z1 - m), e2 = __expf(z2 - m);
        float inv = 1.f / (e0 + e1 + e2);
        wsm[warp][h * 3 + 0] = e0 * inv;
        wsm[warp][h * 3 + 1] = e1 * inv;
        wsm[warp][h * 3 + 2] = e2 * inv;
    }
    __syncwarp();
    #pragma unroll
    for (int u = 0; u < 6; u++) {
        int j = lane * 6 + u;
        int h = j / 24, d = j - h * 24;
        float a = 0.f;
        #pragma unroll
        for (int r = 0; r < 3; r++)
            a = fmaf(wsm[warp][h * 3 + r], g_o[((size_t)(r * 8 + h) * NTOK + row) * 24 + d], a);
        outs[warp][j] = a;
    }
    __syncwarp();
    float xv = 0.f;
    if (lane < 24) {
        float a = bo[lane];
        #pragma unroll 4
        for (int j = 0; j < 192; j++) a = fmaf(outs[warp][j], Wo_s[j * 24 + lane], a);
        xv = x[(size_t)row * 24 + lane] + a;
    }
    float s = (lane < 24) ? xv : 0.f;
    #pragma unroll
    for (int t = 16; t > 0; t >>= 1) s += __shfl_xor_sync(0xffffffffu, s, t);
    float mu = s * (1.f / 24.f);
    float dv = (lane < 24) ? (xv - mu) : 0.f;
    float v2 = dv * dv;
    #pragma unroll
    for (int t = 16; t > 0; t >>= 1) v2 += __shfl_xor_sync(0xffffffffu, v2, t);
    float inv = rsqrtf(v2 * (1.f / 24.f) + 1e-5f);
    if (lane < 24) hsm[warp][lane] = dv * inv * g2[lane] + b2v[lane];
    __syncwarp();
    if (lane < 24) {
        float f = b1v[lane];
        #pragma unroll
        for (int j = 0; j < 24; j++) f = fmaf(hsm[warp][j], W1[j * 24 + lane], f);
        fsm[warp][lane] = fmaxf(f, 0.f);
    }
    __syncwarp();
    if (lane < 24) {
        float f = b2f[lane];
        #pragma unroll
        for (int j = 0; j < 24; j++) f = fmaf(fsm[warp][j], W2[j * 24 + lane], f);
        out[(size_t)row * 24 + lane] = xv + f;
    }
}

extern "C" void kernel_launch(void* const* d_in, const int* in_sizes, int n_in,
                              void* d_out, int out_size) {
    const float* x      = (const float*)d_in[0];
    const float* coords = (const float*)d_in[1];
    const float* n1g    = (const float*)d_in[2];
    const float* n1b    = (const float*)d_in[3];
    const float* Wq     = (const float*)d_in[4];
    const float* Wk     = (const float*)d_in[5];
    const float* Wv     = (const float*)d_in[6];
    const float* wrpe   = (const float*)d_in[7];
    const float* Wo     = (const float*)d_in[8];
    const float* bo     = (const float*)d_in[9];
    const float* n2g    = (const float*)d_in[10];
    const float* n2b    = (const float*)d_in[11];
    const float* W1     = (const float*)d_in[12];
    const float* b1     = (const float*)d_in[13];
    const float* W2     = (const float*)d_in[14];
    const float* b2     = (const float*)d_in[15];
    const float* alphas = (const float*)d_in[16];
    float* out = (float*)d_out;

    k_ln_qkv<<<NTOK / 64, 576>>>(x, n1g, n1b, Wq, Wk, Wv);
    k_build<<<NTOK / 32, 256>>>(coords, alphas, wrpe);

    k_presort<<<NSEG * 8, 512>>>();
    k_gmerge<<<768, 256>>>(8192);
    k_finish<<<NSEG * 8, 512>>>(8192);
    k_gmerge<<<768, 256>>>(16384);
    k_finish<<<NSEG * 8, 512>>>(16384);
    k_gmerge<<<768, 256>>>(32768);
    k_finish<<<NSEG * 8, 512>>>(32768);

    dim3 ag(NTOK / 64, NH, 3);   // 512 x 8 x 3 half-tiles
    k_attn<<<ag, 256>>>();
    k_combine<<<NTOK / 16, 512>>>(x, Wo, bo, n2g, n2b, W1, b1, W2, b2, out);
}

// round 15
// speedup vs baseline: 1.0132x; 1.0132x over previous
#include <cuda_runtime.h>
#include <math.h>

#define NTOK 32768
#define NH 8
#define HD 24
#define HDIM 28
#define NSEG 48
#define CHUNK 4096

typedef unsigned long long ull;

#define FMA_F32X2(d, a, b, c) \
    asm("fma.rn.f32x2 %0, %1, %2, %3;" : "=l"(d) : "l"(a), "l"(b), "l"(c))
#define PACK_F32X2(out, lo, hi) \
    asm("mov.b64 %0, {%1, %2};" : "=l"(out) : "r"(lo), "r"(hi))
#define UNPACK_F32X2(lo, hi, in) \
    asm("mov.b64 {%0, %1}, %2;" : "=r"(lo), "=r"(hi) : "l"(in))

// ---------- scratch ----------
static __device__ float g_v[(size_t)NTOK * 192];                   // dense v: [n][h*24+d]
static __device__ float g_qhat[(size_t)NH * NTOK * HDIM];
static __device__ float g_khat[(size_t)NH * NTOK * HDIM];
static __device__ ull   g_keys[(size_t)NSEG * NTOK];
static __device__ float g_o[(size_t)24 * NTOK * HD];
static __device__ float g_z[(size_t)24 * NTOK];

__device__ __forceinline__ unsigned ford(float f) {
    unsigned u = __float_as_uint(f);
    return (u & 0x80000000u) ? ~u : (u | 0x80000000u);
}

__device__ __forceinline__ void cswap(ull& a, ull& b, bool asc) {
    if ((a > b) == asc) { ull t = a; a = b; b = t; }
}

__device__ __forceinline__ void tail8(ull e[8], bool asc) {
    #pragma unroll
    for (int r = 0; r < 4; r++) cswap(e[r], e[r + 4], asc);
    #pragma unroll
    for (int r = 0; r < 8; r++) if (!(r & 2)) cswap(e[r], e[r | 2], asc);
    #pragma unroll
    for (int r = 0; r < 8; r += 2) cswap(e[r], e[r + 1], asc);
}

template <int K>
__device__ __forceinline__ void reg_tail(ull e[8], int g0) {
    #pragma unroll
    for (int j = (K > 8 ? 4 : K / 2); j > 0; j >>= 1) {
        #pragma unroll
        for (int r = 0; r < 8; r++) {
            if (!(r & j)) {
                bool asc = (((g0 + r) & K) == 0);
                cswap(e[r], e[r | j], asc);
            }
        }
    }
}

__device__ __forceinline__ void spass4(ull* s, int pbase, int j, bool asc) {
    int i = ((pbase & ~(j - 1)) << 1) | (pbase & (j - 1));
    ulonglong2 a0 = *(ulonglong2*)(s + i);
    ulonglong2 a1 = *(ulonglong2*)(s + i + 2);
    ulonglong2 b0 = *(ulonglong2*)(s + i + j);
    ulonglong2 b1 = *(ulonglong2*)(s + i + j + 2);
    cswap(a0.x, b0.x, asc); cswap(a0.y, b0.y, asc);
    cswap(a1.x, b1.x, asc); cswap(a1.y, b1.y, asc);
    *(ulonglong2*)(s + i) = a0;
    *(ulonglong2*)(s + i + 2) = a1;
    *(ulonglong2*)(s + i + j) = b0;
    *(ulonglong2*)(s + i + j + 2) = b1;
}

// ---------- fused LN1 + QKV + q_hat/k_hat + keys ----------
// dynamic smem layout (floats):
//   xnt   [0, 1632)         24 x 68
//   qs    [1632, 13984)     64 x 193
//   ks    [13984, 26336)    64 x 193
//   ksm   [26336 floats = byte 105344)  48 x 64 ull (24576 B)
//   stage [1632, 16480)     8 x 64 x 29 (reuses qs/ks after phase 3a)
#define FUSED_SMEM_BYTES (26336 * 4 + 48 * 64 * 8)
__global__ void __launch_bounds__(576) k_fused(
    const float* __restrict__ x, const float* __restrict__ g1, const float* __restrict__ b1,
    const float* __restrict__ Wq, const float* __restrict__ Wk, const float* __restrict__ Wv,
    const float* __restrict__ coords, const float* __restrict__ alphas,
    const float* __restrict__ Wrpe) {
    extern __shared__ __align__(16) float DS[];
    float* xnt = DS;
    float* qs  = DS + 1632;
    float* ks  = DS + 13984;
    ull*  ksm  = (ull*)(DS + 26336);
    float* stage = DS + 1632;
    __shared__ float wsm[16], wsqm[16];

    int tid = threadIdx.x;
    int base = blockIdx.x * 64;

    if (tid >= 64 && tid < 80) {
        int t = tid - 64;
        int h = t >> 1, c = t & 1;
        float s = 0.f;
        for (int i = 0; i < 24; i++)
            for (int j = 0; j < 8; j++)
                s += Wrpe[(h * 24 + i) * 16 + c * 8 + j];
        s *= (1.f / 192.f);
        wsm[t] = s * s;
        wsqm[t] = sqrtf(2.f * s * s);
    }
    if (tid < 64) {
        int row = base + tid;
        float xv[24];
        float mu = 0.f;
        #pragma unroll
        for (int i = 0; i < 24; i++) { xv[i] = x[(size_t)row * 24 + i]; mu += xv[i]; }
        mu *= (1.f / 24.f);
        float var = 0.f;
        #pragma unroll
        for (int i = 0; i < 24; i++) { float d = xv[i] - mu; var += d * d; }
        var *= (1.f / 24.f);
        float inv = rsqrtf(var + 1e-5f);
        #pragma unroll
        for (int i = 0; i < 24; i++) xnt[i * 68 + tid] = (xv[i] - mu) * inv * g1[i] + b1[i];
    }
    __syncthreads();

    // phase 2: one output column per thread
    {
        int col = tid;
        const float* W;
        int cc;
        if (col < 192)      { W = Wq; cc = col; }
        else if (col < 384) { W = Wk; cc = col - 192; }
        else                { W = Wv; cc = col - 384; }
        float w[24];
        #pragma unroll
        for (int i = 0; i < 24; i++) w[i] = W[i * 192 + cc];
        #pragma unroll 2
        for (int r4 = 0; r4 < 16; r4++) {
            float a0 = 0.f, a1 = 0.f, a2 = 0.f, a3 = 0.f;
            #pragma unroll
            for (int i = 0; i < 24; i++) {
                float4 xr = *(const float4*)&xnt[i * 68 + r4 * 4];
                a0 = fmaf(xr.x, w[i], a0);
                a1 = fmaf(xr.y, w[i], a1);
                a2 = fmaf(xr.z, w[i], a2);
                a3 = fmaf(xr.w, w[i], a3);
            }
            int row = r4 * 4;
            if (col < 192) {
                qs[(row    ) * 193 + col] = a0;
                qs[(row + 1) * 193 + col] = a1;
                qs[(row + 2) * 193 + col] = a2;
                qs[(row + 3) * 193 + col] = a3;
            } else if (col < 384) {
                int c2 = col - 192;
                ks[(row    ) * 193 + c2] = a0;
                ks[(row + 1) * 193 + c2] = a1;
                ks[(row + 2) * 193 + c2] = a2;
                ks[(row + 3) * 193 + c2] = a3;
            } else {
                int c2 = col - 384;
                size_t o = (size_t)(base + row) * 192 + c2;
                g_v[o] = a0;
                g_v[o + 192] = a1;
                g_v[o + 384] = a2;
                g_v[o + 576] = a3;
            }
        }
    }
    __syncthreads();

    // phase 3a: q_hat/k_hat in registers + keys to smem
    float qh[HDIM], kh[HDIM];
    int h = tid >> 6, tok = tid & 63;
    bool valid = tid < 512;
    if (valid) {
        int n = base + tok;
        float p0 = coords[n * 3 + 1], p1 = coords[n * 3 + 2];
        float sqn = wsm[h * 2] * p0 * p0 + wsm[h * 2 + 1] * p1 * p1;
        float qp0 = wsqm[h * 2] * p0, qp1 = wsqm[h * 2 + 1] * p1;
        const float qscale = 0.2041241452319315f;
        #pragma unroll
        for (int i = 0; i < 24; i++) {
            qh[i] = qs[tok * 193 + h * 24 + i] * qscale;
            kh[i] = ks[tok * 193 + h * 24 + i];
        }
        qh[24] = qp0; qh[25] = qp1; qh[26] = -sqn; qh[27] = 1.f;
        kh[24] = qp0; kh[25] = qp1; kh[26] = 1.f;  kh[27] = -sqn;
        #pragma unroll
        for (int r = 0; r < 3; r++) {
            const float* a = &alphas[(r * 8 + h) * HDIM];
            float sq = 0.f, sk = 0.f;
            #pragma unroll
            for (int i = 0; i < HDIM; i++) { sq = fmaf(qh[i], a[i], sq); sk = fmaf(kh[i], a[i], sk); }
            ksm[(r * 8 + h) * 64 + tok] = ((ull)ford(sq) << 32) | (unsigned)n;
            ksm[(24 + r * 8 + h) * 64 + tok] = ((ull)ford(sk) << 32) | (unsigned)n;
        }
    }
    __syncthreads();

    // phase 3b: stage + coalesced flush (q_hat, then k_hat)
    if (valid) {
        #pragma unroll
        for (int i = 0; i < HDIM; i++) stage[h * 1856 + tok * 29 + i] = qh[i];
    }
    __syncthreads();
    for (int e = tid; e < 8 * 1792; e += 576) {
        int hh = e / 1792, rr = e - hh * 1792;
        g_qhat[(size_t)hh * NTOK * 28 + (size_t)base * 28 + rr] =
            stage[hh * 1856 + (rr / 28) * 29 + rr % 28];
    }
    __syncthreads();
    if (valid) {
        #pragma unroll
        for (int i = 0; i < HDIM; i++) stage[h * 1856 + tok * 29 + i] = kh[i];
    }
    __syncthreads();
    for (int e = tid; e < 8 * 1792; e += 576) {
        int hh = e / 1792, rr = e - hh * 1792;
        g_khat[(size_t)hh * NTOK * 28 + (size_t)base * 28 + rr] =
            stage[hh * 1856 + (rr / 28) * 29 + rr % 28];
    }
    for (int e = tid; e < 48 * 64; e += 576) {
        int seg = e >> 6, nn = e & 63;
        g_keys[(size_t)seg * NTOK + base + nn] = ksm[e];
    }
}

// ---------- bitonic: presort ----------
__global__ void __launch_bounds__(512) k_presort() {
    __shared__ __align__(16) ull s[CHUNK];
    int seg = blockIdx.x >> 3, chunk = blockIdx.x & 7;
    size_t gb = (size_t)seg * NTOK + (size_t)chunk * CHUNK;
    int base = chunk * CHUNK;
    int t = threadIdx.x;
    int e0 = t * 8;
    int g0 = base + e0;

    ull e[8];
    #pragma unroll
    for (int r = 0; r < 8; r++) e[r] = g_keys[gb + e0 + r];
    reg_tail<2>(e, g0);
    reg_tail<4>(e, g0);
    reg_tail<8>(e, g0);
    #pragma unroll
    for (int r = 0; r < 8; r++) s[e0 + r] = e[r];
    __syncthreads();

    for (int k = 16; k <= CHUNK; k <<= 1) {
        for (int j = k >> 1; j >= 8; j >>= 1) {
            int pbase = t * 4;
            int i = ((pbase & ~(j - 1)) << 1) | (pbase & (j - 1));
            bool asc = (((base + i) & k) == 0);
            spass4(s, pbase, j, asc);
            __syncthreads();
        }
        #pragma unroll
        for (int r = 0; r < 8; r++) e[r] = s[e0 + r];
        bool asc = ((g0 & k) == 0);
        tail8(e, asc);
        if (k < CHUNK) {
            #pragma unroll
            for (int r = 0; r < 8; r++) s[e0 + r] = e[r];
            __syncthreads();
        }
    }
    #pragma unroll
    for (int r = 0; r < 8; r++) g_keys[gb + e0 + r] = e[r];
}

// ---------- fused global merge ----------
__global__ void __launch_bounds__(256) k_gmerge(int k) {
    int t = blockIdx.x * 256 + threadIdx.x;
    int seg = t >> 12;
    int g = t & 4095;
    size_t bs = (size_t)seg * NTOK;
    ull e[8];
    #pragma unroll
    for (int m = 0; m < 8; m++) e[m] = g_keys[bs + g + 4096 * m];
    #pragma unroll
    for (int j = 4; j >= 1; j >>= 1) {
        if (j * 8192 <= k) {
            #pragma unroll
            for (int m = 0; m < 8; m++) {
                if (!(m & j)) {
                    bool asc = (((m * 4096) & k) == 0);
                    cswap(e[m], e[m + j], asc);
                }
            }
        }
    }
    #pragma unroll
    for (int m = 0; m < 8; m++) g_keys[bs + g + 4096 * m] = e[m];
}

// ---------- bitonic: finish ----------
__global__ void __launch_bounds__(512) k_finish(int k) {
    __shared__ __align__(16) ull s[CHUNK];
    int seg = blockIdx.x >> 3, chunk = blockIdx.x & 7;
    size_t gb = (size_t)seg * NTOK + (size_t)chunk * CHUNK;
    int base = chunk * CHUNK;
    int t = threadIdx.x;
    int e0 = t * 8;
    #pragma unroll
    for (int u = 0; u < 2; u++) {
        int i = (t + u * 512) * 4;
        *(ulonglong2*)(s + i)     = *(const ulonglong2*)(g_keys + gb + i);
        *(ulonglong2*)(s + i + 2) = *(const ulonglong2*)(g_keys + gb + i + 2);
    }
    __syncthreads();
    bool asc = ((base & k) == 0);
    for (int j = CHUNK >> 1; j >= 8; j >>= 1) {
        spass4(s, t * 4, j, asc);
        __syncthreads();
    }
    ull e[8];
    #pragma unroll
    for (int r = 0; r < 8; r++) e[r] = s[e0 + r];
    tail8(e, asc);
    #pragma unroll
    for (int r = 0; r < 8; r++) g_keys[gb + e0 + r] = e[r];
}

// ---------- block attention v3 (R12-exact, v from g_v) ----------
__global__ void __launch_bounds__(512) k_attn() {
    __shared__ __align__(16) float SP[11072];
    float* qs_t = SP;                          // [kk][row] 28 x 130
    float* ks   = SP + 3648;                   // [row][kk] 128 x 30
    float* vs   = SP + 7488;                   // [row][d]  128 x 26
    int* qidx = (int*)(SP + 10816);
    int* kidx = (int*)(SP + 10944);
    float* pbuf = SP;                          // [32 cols][rowpair], 32 x 134

    int tid = threadIdx.x;
    int b = blockIdx.x, h = blockIdx.y, r = blockIdx.z;
    int seg = r * 8 + h;

    if (tid < 128)
        qidx[tid] = (int)(g_keys[(size_t)seg * NTOK + b * 128 + tid] & 0xffffffffu);
    else if (tid < 256) {
        int t = tid - 128;
        kidx[t] = (int)(g_keys[(size_t)(24 + seg) * NTOK + b * 128 + t] & 0xffffffffu);
    }
    __syncthreads();
    for (int i = tid; i < 128 * 28; i += 512) {
        int row = i / 28, kk = i - row * 28;
        qs_t[kk * 130 + row] = g_qhat[((size_t)h * NTOK + qidx[row]) * HDIM + kk];
        ks[row * 30 + kk]    = g_khat[((size_t)h * NTOK + kidx[row]) * HDIM + kk];
    }
    for (int i = tid; i < 128 * 24; i += 512) {
        int row = i / 24, kk = i - row * 24;
        vs[row * 26 + kk] = g_v[(size_t)kidx[row] * 192 + h * 24 + kk];
    }
    __syncthreads();

    int ty = tid >> 4, tx = tid & 15;
    int R0 = ty * 4;
    ull acc2[2][8];
    #pragma unroll
    for (int u = 0; u < 2; u++)
        #pragma unroll
        for (int c = 0; c < 8; c++) acc2[u][c] = 0ULL;

    #pragma unroll 2
    for (int kk = 0; kk < 28; kk++) {
        ull qp0 = *(const ull*)&qs_t[kk * 130 + R0];
        ull qp1 = *(const ull*)&qs_t[kk * 130 + R0 + 2];
        #pragma unroll
        for (int c = 0; c < 8; c++) {
            float kv = ks[(tx + 16 * c) * 30 + kk];
            unsigned kb = __float_as_uint(kv);
            ull kp;
            PACK_F32X2(kp, kb, kb);
            FMA_F32X2(acc2[0][c], qp0, kp, acc2[0][c]);
            FMA_F32X2(acc2[1][c], qp1, kp, acc2[1][c]);
        }
    }

    #pragma unroll
    for (int u = 0; u < 2; u++) {
        float vlo[8], vhi[8];
        #pragma unroll
        for (int c = 0; c < 8; c++) {
            unsigned lo, hi;
            UNPACK_F32X2(lo, hi, acc2[u][c]);
            vlo[c] = __uint_as_float(lo);
            vhi[c] = __uint_as_float(hi);
        }
        float mlo = vlo[0], mhi = vhi[0];
        #pragma unroll
        for (int c = 1; c < 8; c++) { mlo = fmaxf(mlo, vlo[c]); mhi = fmaxf(mhi, vhi[c]); }
        #pragma unroll
        for (int s = 1; s < 16; s <<= 1) {
            mlo = fmaxf(mlo, __shfl_xor_sync(0xffffffffu, mlo, s));
            mhi = fmaxf(mhi, __shfl_xor_sync(0xffffffffu, mhi, s));
        }
        float slo = 0.f, shi = 0.f;
        #pragma unroll
        for (int c = 0; c < 8; c++) {
            vlo[c] = __expf(vlo[c] - mlo); slo += vlo[c];
            vhi[c] = __expf(vhi[c] - mhi); shi += vhi[c];
        }
        #pragma unroll
        for (int s = 1; s < 16; s <<= 1) {
            slo += __shfl_xor_sync(0xffffffffu, slo, s);
            shi += __shfl_xor_sync(0xffffffffu, shi, s);
        }
        float ilo = 1.f / slo, ihi = 1.f / shi;
        #pragma unroll
        for (int c = 0; c < 8; c++) {
            unsigned lo = __float_as_uint(vlo[c] * ilo);
            unsigned hi = __float_as_uint(vhi[c] * ihi);
            PACK_F32X2(acc2[u][c], lo, hi);
        }
        if (tx == 0) {
            g_z[(size_t)seg * NTOK + qidx[R0 + 2 * u]]     = __logf(slo) + mlo;
            g_z[(size_t)seg * NTOK + qidx[R0 + 2 * u + 1]] = __logf(shi) + mhi;
        }
    }

    int s = tid & 63;
    int dg = tid >> 6;
    ull oap[3];
    #pragma unroll
    for (int d = 0; d < 3; d++) oap[d] = 0ULL;

    for (int round = 0; round < 4; round++) {
        __syncthreads();
        #pragma unroll
        for (int cc2 = 0; cc2 < 2; cc2++) {
            int cc = round * 2 + cc2;
            int lc = tx + 16 * cc2;
            *(ull*)&pbuf[lc * 134 + R0]     = acc2[0][cc];
            *(ull*)&pbuf[lc * 134 + R0 + 2] = acc2[1][cc];
        }
        __syncthreads();
        #pragma unroll 4
        for (int c16 = 0; c16 < 32; c16++) {
            ull pp = *(const ull*)&pbuf[c16 * 134 + 2 * s];
            int gcol = round * 32 + c16;
            const float* vv = &vs[gcol * 26 + dg * 3];
            #pragma unroll
            for (int d = 0; d < 3; d++) {
                unsigned vb = __float_as_uint(vv[d]);
                ull vp;
                PACK_F32X2(vp, vb, vb);
                FMA_F32X2(oap[d], pp, vp, oap[d]);
            }
        }
    }
    {
        int n0 = qidx[2 * s], n1 = qidx[2 * s + 1];
        float* o0 = &g_o[((size_t)seg * NTOK + n0) * 24 + dg * 3];
        float* o1 = &g_o[((size_t)seg * NTOK + n1) * 24 + dg * 3];
        #pragma unroll
        for (int d = 0; d < 3; d++) {
            unsigned lo, hi;
            UNPACK_F32X2(lo, hi, oap[d]);
            o0[d] = __uint_as_float(lo);
            o1[d] = __uint_as_float(hi);
        }
    }
}

// ---------- combine ----------
__global__ void __launch_bounds__(512) k_combine(
    const float* __restrict__ x, const float* __restrict__ Wo, const float* __restrict__ bo,
    const float* __restrict__ g2, const float* __restrict__ b2v,
    const float* __restrict__ W1, const float* __restrict__ b1v,
    const float* __restrict__ W2, const float* __restrict__ b2f,
    float* __restrict__ out) {
    __shared__ float Wo_s[4608];
    __shared__ float outs[16][192];
    __shared__ float wsm[16][24];
    __shared__ float hsm[16][24];
    __shared__ float fsm[16][24];
    int warp = threadIdx.x >> 5, lane = threadIdx.x & 31;
    int row = blockIdx.x * 16 + warp;

    for (int i = threadIdx.x; i < 4608; i += 512) Wo_s[i] = Wo[i];
    __syncthreads();

    if (lane < 8) {
        int h = lane;
        float z0 = g_z[(size_t)h * NTOK + row];
        float z1 = g_z[(size_t)(8 + h) * NTOK + row];
        float z2 = g_z[(size_t)(16 + h) * NTOK + row];
        float m = fmaxf(z0, fmaxf(z1, z2));
        float e0 = __expf(z0 - m), e1 = __expf(z1 - m), e2 = __expf(z2 - m);
        float inv = 1.f / (e0 + e1 + e2);
        wsm[warp][h * 3 + 0] = e0 * inv;
        wsm[warp][h * 3 + 1] = e1 * inv;
        wsm[warp][h * 3 + 2] = e2 * inv;
    }
    __syncwarp();
    #pragma unroll
    for (int u = 0; u < 6; u++) {
        int j = lane * 6 + u;
        int h = j / 24, d = j - h * 24;
        float a = 0.f;
        #pragma unroll
        for (int r = 0; r < 3; r++)
            a = fmaf(wsm[warp][h * 3 + r], g_o[((size_t)(r * 8 + h) * NTOK + row) * 24 + d], a);
        outs[warp][j] = a;
    }
    __syncwarp();
    float xv = 0.f;
    if (lane < 24) {
        float a = bo[lane];
        #pragma unroll 4
        for (int j = 0; j < 192; j++) a = fmaf(outs[warp][j], Wo_s[j * 24 + lane], a);
        xv = x[(size_t)row * 24 + lane] + a;
    }
    float s = (lane < 24) ? xv : 0.f;
    #pragma unroll
    for (int t = 16; t > 0; t >>= 1) s += __shfl_xor_sync(0xffffffffu, s, t);
    float mu = s * (1.f / 24.f);
    float dv = (lane < 24) ? (xv - mu) : 0.f;
    float v2 = dv * dv;
    #pragma unroll
    for (int t = 16; t > 0; t >>= 1) v2 += __shfl_xor_sync(0xffffffffu, v2, t);
    float inv = rsqrtf(v2 * (1.f / 24.f) + 1e-5f);
    if (lane < 24) hsm[warp][lane] = dv * inv * g2[lane] + b2v[lane];
    __syncwarp();
    if (lane < 24) {
        float f = b1v[lane];
        #pragma unroll
        for (int j = 0; j < 24; j++) f = fmaf(hsm[warp][j], W1[j * 24 + lane], f);
        fsm[warp][lane] = fmaxf(f, 0.f);
    }
    __syncwarp();
    if (lane < 24) {
        float f = b2f[lane];
        #pragma unroll
        for (int j = 0; j < 24; j++) f = fmaf(fsm[warp][j], W2[j * 24 + lane], f);
        out[(size_t)row * 24 + lane] = xv + f;
    }
}

extern "C" void kernel_launch(void* const* d_in, const int* in_sizes, int n_in,
                              void* d_out, int out_size) {
    const float* x      = (const float*)d_in[0];
    const float* coords = (const float*)d_in[1];
    const float* n1g    = (const float*)d_in[2];
    const float* n1b    = (const float*)d_in[3];
    const float* Wq     = (const float*)d_in[4];
    const float* Wk     = (const float*)d_in[5];
    const float* Wv     = (const float*)d_in[6];
    const float* wrpe   = (const float*)d_in[7];
    const float* Wo     = (const float*)d_in[8];
    const float* bo     = (const float*)d_in[9];
    const float* n2g    = (const float*)d_in[10];
    const float* n2b    = (const float*)d_in[11];
    const float* W1     = (const float*)d_in[12];
    const float* b1     = (const float*)d_in[13];
    const float* W2     = (const float*)d_in[14];
    const float* b2     = (const float*)d_in[15];
    const float* alphas = (const float*)d_in[16];
    float* out = (float*)d_out;

    cudaFuncSetAttribute(k_fused, cudaFuncAttributeMaxDynamicSharedMemorySize,
                         FUSED_SMEM_BYTES);

    k_fused<<<NTOK / 64, 576, FUSED_SMEM_BYTES>>>(x, n1g, n1b, Wq, Wk, Wv,
                                                  coords, alphas, wrpe);

    k_presort<<<NSEG * 8, 512>>>();
    k_gmerge<<<768, 256>>>(8192);
    k_finish<<<NSEG * 8, 512>>>(8192);
    k_gmerge<<<768, 256>>>(16384);
    k_finish<<<NSEG * 8, 512>>>(16384);
    k_gmerge<<<768, 256>>>(32768);
    k_finish<<<NSEG * 8, 512>>>(32768);

    dim3 ag(NTOK / 128, NH, 3);
    k_attn<<<ag, 512>>>();
    k_combine<<<NTOK / 16, 512>>>(x, Wo, bo, n2g, n2b, W1, b1, W2, b2, out);
}

// round 16
// speedup vs baseline: 1.0242x; 1.0108x over previous
#include <cuda_runtime.h>
#include <math.h>

#define NTOK 32768
#define NH 8
#define HD 24
#define HDIM 28
#define NSEG 48
#define CHUNK 4096

typedef unsigned long long ull;

#define FMA_F32X2(d, a, b, c) \
    asm("fma.rn.f32x2 %0, %1, %2, %3;" : "=l"(d) : "l"(a), "l"(b), "l"(c))
#define PACK_F32X2(out, lo, hi) \
    asm("mov.b64 %0, {%1, %2};" : "=l"(out) : "r"(lo), "r"(hi))
#define UNPACK_F32X2(lo, hi, in) \
    asm("mov.b64 {%0, %1}, %2;" : "=r"(lo), "=r"(hi) : "l"(in))

// ---------- scratch ----------
static __device__ float g_v[(size_t)NTOK * 192];
static __device__ float g_qhat[(size_t)NH * NTOK * HDIM];
static __device__ float g_khat[(size_t)NH * NTOK * HDIM];
static __device__ ull   g_keys[(size_t)NSEG * NTOK];
static __device__ float g_o[(size_t)24 * NTOK * HD];
static __device__ float g_z[(size_t)24 * NTOK];

__device__ __forceinline__ unsigned ford(float f) {
    unsigned u = __float_as_uint(f);
    return (u & 0x80000000u) ? ~u : (u | 0x80000000u);
}

__device__ __forceinline__ void cswap(ull& a, ull& b, bool asc) {
    if ((a > b) == asc) { ull t = a; a = b; b = t; }
}

__device__ __forceinline__ void tail8(ull e[8], bool asc) {
    #pragma unroll
    for (int r = 0; r < 4; r++) cswap(e[r], e[r + 4], asc);
    #pragma unroll
    for (int r = 0; r < 8; r++) if (!(r & 2)) cswap(e[r], e[r | 2], asc);
    #pragma unroll
    for (int r = 0; r < 8; r += 2) cswap(e[r], e[r + 1], asc);
}

template <int K>
__device__ __forceinline__ void reg_tail(ull e[8], int g0) {
    #pragma unroll
    for (int j = (K > 8 ? 4 : K / 2); j > 0; j >>= 1) {
        #pragma unroll
        for (int r = 0; r < 8; r++) {
            if (!(r & j)) {
                bool asc = (((g0 + r) & K) == 0);
                cswap(e[r], e[r | j], asc);
            }
        }
    }
}

__device__ __forceinline__ void spass4(ull* s, int pbase, int j, bool asc) {
    int i = ((pbase & ~(j - 1)) << 1) | (pbase & (j - 1));
    ulonglong2 a0 = *(ulonglong2*)(s + i);
    ulonglong2 a1 = *(ulonglong2*)(s + i + 2);
    ulonglong2 b0 = *(ulonglong2*)(s + i + j);
    ulonglong2 b1 = *(ulonglong2*)(s + i + j + 2);
    cswap(a0.x, b0.x, asc); cswap(a0.y, b0.y, asc);
    cswap(a1.x, b1.x, asc); cswap(a1.y, b1.y, asc);
    *(ulonglong2*)(s + i) = a0;
    *(ulonglong2*)(s + i + 2) = a1;
    *(ulonglong2*)(s + i + j) = b0;
    *(ulonglong2*)(s + i + j + 2) = b1;
}

// ---------- fused LN1 + QKV + q_hat/k_hat + keys ----------
#define FUSED_SMEM_BYTES (26336 * 4 + 48 * 64 * 8)
__global__ void __launch_bounds__(576) k_fused(
    const float* __restrict__ x, const float* __restrict__ g1, const float* __restrict__ b1,
    const float* __restrict__ Wq, const float* __restrict__ Wk, const float* __restrict__ Wv,
    const float* __restrict__ coords, const float* __restrict__ alphas,
    const float* __restrict__ Wrpe) {
    extern __shared__ __align__(16) float DS[];
    float* xnt = DS;
    float* qs  = DS + 1632;
    float* ks  = DS + 13984;
    ull*  ksm  = (ull*)(DS + 26336);
    float* stage = DS + 1632;
    __shared__ float wsm[16], wsqm[16];

    int tid = threadIdx.x;
    int base = blockIdx.x * 64;

    if (tid >= 64 && tid < 80) {
        int t = tid - 64;
        int h = t >> 1, c = t & 1;
        float s = 0.f;
        for (int i = 0; i < 24; i++)
            for (int j = 0; j < 8; j++)
                s += Wrpe[(h * 24 + i) * 16 + c * 8 + j];
        s *= (1.f / 192.f);
        wsm[t] = s * s;
        wsqm[t] = sqrtf(2.f * s * s);
    }
    if (tid < 64) {
        int row = base + tid;
        float xv[24];
        float mu = 0.f;
        #pragma unroll
        for (int i = 0; i < 24; i++) { xv[i] = x[(size_t)row * 24 + i]; mu += xv[i]; }
        mu *= (1.f / 24.f);
        float var = 0.f;
        #pragma unroll
        for (int i = 0; i < 24; i++) { float d = xv[i] - mu; var += d * d; }
        var *= (1.f / 24.f);
        float inv = rsqrtf(var + 1e-5f);
        #pragma unroll
        for (int i = 0; i < 24; i++) xnt[i * 68 + tid] = (xv[i] - mu) * inv * g1[i] + b1[i];
    }
    __syncthreads();

    {
        int col = tid;
        const float* W;
        int cc;
        if (col < 192)      { W = Wq; cc = col; }
        else if (col < 384) { W = Wk; cc = col - 192; }
        else                { W = Wv; cc = col - 384; }
        float w[24];
        #pragma unroll
        for (int i = 0; i < 24; i++) w[i] = W[i * 192 + cc];
        #pragma unroll 2
        for (int r4 = 0; r4 < 16; r4++) {
            float a0 = 0.f, a1 = 0.f, a2 = 0.f, a3 = 0.f;
            #pragma unroll
            for (int i = 0; i < 24; i++) {
                float4 xr = *(const float4*)&xnt[i * 68 + r4 * 4];
                a0 = fmaf(xr.x, w[i], a0);
                a1 = fmaf(xr.y, w[i], a1);
                a2 = fmaf(xr.z, w[i], a2);
                a3 = fmaf(xr.w, w[i], a3);
            }
            int row = r4 * 4;
            if (col < 192) {
                qs[(row    ) * 193 + col] = a0;
                qs[(row + 1) * 193 + col] = a1;
                qs[(row + 2) * 193 + col] = a2;
                qs[(row + 3) * 193 + col] = a3;
            } else if (col < 384) {
                int c2 = col - 192;
                ks[(row    ) * 193 + c2] = a0;
                ks[(row + 1) * 193 + c2] = a1;
                ks[(row + 2) * 193 + c2] = a2;
                ks[(row + 3) * 193 + c2] = a3;
            } else {
                int c2 = col - 384;
                size_t o = (size_t)(base + row) * 192 + c2;
                g_v[o] = a0;
                g_v[o + 192] = a1;
                g_v[o + 384] = a2;
                g_v[o + 576] = a3;
            }
        }
    }
    __syncthreads();

    float qh[HDIM], kh[HDIM];
    int h = tid >> 6, tok = tid & 63;
    bool valid = tid < 512;
    if (valid) {
        int n = base + tok;
        float p0 = coords[n * 3 + 1], p1 = coords[n * 3 + 2];
        float sqn = wsm[h * 2] * p0 * p0 + wsm[h * 2 + 1] * p1 * p1;
        float qp0 = wsqm[h * 2] * p0, qp1 = wsqm[h * 2 + 1] * p1;
        const float qscale = 0.2041241452319315f;
        #pragma unroll
        for (int i = 0; i < 24; i++) {
            qh[i] = qs[tok * 193 + h * 24 + i] * qscale;
            kh[i] = ks[tok * 193 + h * 24 + i];
        }
        qh[24] = qp0; qh[25] = qp1; qh[26] = -sqn; qh[27] = 1.f;
        kh[24] = qp0; kh[25] = qp1; kh[26] = 1.f;  kh[27] = -sqn;
        #pragma unroll
        for (int r = 0; r < 3; r++) {
            const float* a = &alphas[(r * 8 + h) * HDIM];
            float sq = 0.f, sk = 0.f;
            #pragma unroll
            for (int i = 0; i < HDIM; i++) { sq = fmaf(qh[i], a[i], sq); sk = fmaf(kh[i], a[i], sk); }
            ksm[(r * 8 + h) * 64 + tok] = ((ull)ford(sq) << 32) | (unsigned)n;
            ksm[(24 + r * 8 + h) * 64 + tok] = ((ull)ford(sk) << 32) | (unsigned)n;
        }
    }
    __syncthreads();

    if (valid) {
        #pragma unroll
        for (int i = 0; i < HDIM; i++) stage[h * 1856 + tok * 29 + i] = qh[i];
    }
    __syncthreads();
    for (int e = tid; e < 8 * 1792; e += 576) {
        int hh = e / 1792, rr = e - hh * 1792;
        g_qhat[(size_t)hh * NTOK * 28 + (size_t)base * 28 + rr] =
            stage[hh * 1856 + (rr / 28) * 29 + rr % 28];
    }
    __syncthreads();
    if (valid) {
        #pragma unroll
        for (int i = 0; i < HDIM; i++) stage[h * 1856 + tok * 29 + i] = kh[i];
    }
    __syncthreads();
    for (int e = tid; e < 8 * 1792; e += 576) {
        int hh = e / 1792, rr = e - hh * 1792;
        g_khat[(size_t)hh * NTOK * 28 + (size_t)base * 28 + rr] =
            stage[hh * 1856 + (rr / 28) * 29 + rr % 28];
    }
    for (int e = tid; e < 48 * 64; e += 576) {
        int seg = e >> 6, nn = e & 63;
        g_keys[(size_t)seg * NTOK + base + nn] = ksm[e];
    }
}

// ---------- bitonic: presort (k=2..4096) ----------
__global__ void __launch_bounds__(512) k_presort() {
    __shared__ __align__(16) ull s[CHUNK];
    int seg = blockIdx.x >> 3, chunk = blockIdx.x & 7;
    size_t gb = (size_t)seg * NTOK + (size_t)chunk * CHUNK;
    int base = chunk * CHUNK;
    int t = threadIdx.x;
    int e0 = t * 8;
    int g0 = base + e0;

    ull e[8];
    #pragma unroll
    for (int r = 0; r < 8; r++) e[r] = g_keys[gb + e0 + r];
    reg_tail<2>(e, g0);
    reg_tail<4>(e, g0);
    reg_tail<8>(e, g0);
    #pragma unroll
    for (int r = 0; r < 8; r++) s[e0 + r] = e[r];
    __syncthreads();

    for (int k = 16; k <= CHUNK; k <<= 1) {
        for (int j = k >> 1; j >= 8; j >>= 1) {
            int pbase = t * 4;
            int i = ((pbase & ~(j - 1)) << 1) | (pbase & (j - 1));
            bool asc = (((base + i) & k) == 0);
            spass4(s, pbase, j, asc);
            __syncthreads();
        }
        #pragma unroll
        for (int r = 0; r < 8; r++) e[r] = s[e0 + r];
        bool asc = ((g0 & k) == 0);
        tail8(e, asc);
        if (k < CHUNK) {
            #pragma unroll
            for (int r = 0; r < 8; r++) s[e0 + r] = e[r];
            __syncthreads();
        }
    }
    #pragma unroll
    for (int r = 0; r < 8; r++) g_keys[gb + e0 + r] = e[r];
}

// ---------- global top passes: element j in {16384, 8192} for stage k ----------
__global__ void __launch_bounds__(256) k_gtop(int k) {
    int t = blockIdx.x * 256 + threadIdx.x;
    int seg = t >> 12;
    int g = t & 4095;
    size_t bs = (size_t)seg * NTOK;
    ull e[8];
    #pragma unroll
    for (int m = 0; m < 8; m++) e[m] = g_keys[bs + g + 4096 * m];
    #pragma unroll
    for (int jm = 4; jm >= 2; jm >>= 1) {      // element stride jm*4096
        if (jm * 8192 <= k) {
            #pragma unroll
            for (int m = 0; m < 8; m++) {
                if (!(m & jm)) {
                    bool asc = (((m * 4096) & k) == 0);
                    cswap(e[m], e[m + jm], asc);
                }
            }
        }
    }
    #pragma unroll
    for (int m = 0; m < 8; m++) g_keys[bs + g + 4096 * m] = e[m];
}

// ---------- global mid passes: j = 4096,2048,1024 inside 8192-windows ----------
__global__ void __launch_bounds__(256) k_gmid(int k) {
    int t = blockIdx.x * 256 + threadIdx.x;
    int seg = t >> 12;                  // 4096 threads per segment
    int rem = t & 4095;
    int w = rem >> 10, g = rem & 1023;  // window 0..3, lane 0..1023
    size_t base = (size_t)seg * NTOK + (size_t)w * 8192;
    bool asc = (((w * 8192) & k) == 0); // uniform per window (k >= 8192)
    ull e[8];
    #pragma unroll
    for (int m = 0; m < 8; m++) e[m] = g_keys[base + g + 1024 * m];
    tail8(e, asc);                      // j = 4096, 2048, 1024 (element strides 4,2,1 x1024)
    #pragma unroll
    for (int m = 0; m < 8; m++) g_keys[base + g + 1024 * m] = e[m];
}

// ---------- finish: j = 512..1 inside 1024-windows (2 windows per CTA) ----------
__global__ void __launch_bounds__(256) k_finish(int k) {
    __shared__ __align__(16) ull s[2048];
    int seg = blockIdx.x >> 4, blk = blockIdx.x & 15;
    size_t gb = (size_t)seg * NTOK + (size_t)blk * 2048;
    int base = blk * 2048;
    int t = threadIdx.x;
    int e0 = t * 8;
    {
        int i = t * 4;
        *(ulonglong2*)(s + i)        = *(const ulonglong2*)(g_keys + gb + i);
        *(ulonglong2*)(s + i + 2)    = *(const ulonglong2*)(g_keys + gb + i + 2);
        *(ulonglong2*)(s + i + 1024) = *(const ulonglong2*)(g_keys + gb + i + 1024);
        *(ulonglong2*)(s + i + 1026) = *(const ulonglong2*)(g_keys + gb + i + 1026);
    }
    __syncthreads();
    for (int j = 512; j >= 8; j >>= 1) {
        int pbase = t * 4;
        int i = ((pbase & ~(j - 1)) << 1) | (pbase & (j - 1));
        bool asc = (((base + i) & k) == 0);
        spass4(s, pbase, j, asc);
        __syncthreads();
    }
    ull e[8];
    #pragma unroll
    for (int r = 0; r < 8; r++) e[r] = s[e0 + r];
    bool asc = (((base + e0) & k) == 0);
    tail8(e, asc);
    #pragma unroll
    for (int r = 0; r < 8; r++) g_keys[gb + e0 + r] = e[r];
}

// ---------- block attention v3 (R12-exact, v from g_v) ----------
__global__ void __launch_bounds__(512) k_attn() {
    __shared__ __align__(16) float SP[11072];
    float* qs_t = SP;
    float* ks   = SP + 3648;
    float* vs   = SP + 7488;
    int* qidx = (int*)(SP + 10816);
    int* kidx = (int*)(SP + 10944);
    float* pbuf = SP;

    int tid = threadIdx.x;
    int b = blockIdx.x, h = blockIdx.y, r = blockIdx.z;
    int seg = r * 8 + h;

    if (tid < 128)
        qidx[tid] = (int)(g_keys[(size_t)seg * NTOK + b * 128 + tid] & 0xffffffffu);
    else if (tid < 256) {
        int t = tid - 128;
        kidx[t] = (int)(g_keys[(size_t)(24 + seg) * NTOK + b * 128 + t] & 0xffffffffu);
    }
    __syncthreads();
    for (int i = tid; i < 128 * 28; i += 512) {
        int row = i / 28, kk = i - row * 28;
        qs_t[kk * 130 + row] = g_qhat[((size_t)h * NTOK + qidx[row]) * HDIM + kk];
        ks[row * 30 + kk]    = g_khat[((size_t)h * NTOK + kidx[row]) * HDIM + kk];
    }
    for (int i = tid; i < 128 * 24; i += 512) {
        int row = i / 24, kk = i - row * 24;
        vs[row * 26 + kk] = g_v[(size_t)kidx[row] * 192 + h * 24 + kk];
    }
    __syncthreads();

    int ty = tid >> 4, tx = tid & 15;
    int R0 = ty * 4;
    ull acc2[2][8];
    #pragma unroll
    for (int u = 0; u < 2; u++)
        #pragma unroll
        for (int c = 0; c < 8; c++) acc2[u][c] = 0ULL;

    #pragma unroll 2
    for (int kk = 0; kk < 28; kk++) {
        ull qp0 = *(const ull*)&qs_t[kk * 130 + R0];
        ull qp1 = *(const ull*)&qs_t[kk * 130 + R0 + 2];
        #pragma unroll
        for (int c = 0; c < 8; c++) {
            float kv = ks[(tx + 16 * c) * 30 + kk];
            unsigned kb = __float_as_uint(kv);
            ull kp;
            PACK_F32X2(kp, kb, kb);
            FMA_F32X2(acc2[0][c], qp0, kp, acc2[0][c]);
            FMA_F32X2(acc2[1][c], qp1, kp, acc2[1][c]);
        }
    }

    #pragma unroll
    for (int u = 0; u < 2; u++) {
        float vlo[8], vhi[8];
        #pragma unroll
        for (int c = 0; c < 8; c++) {
            unsigned lo, hi;
            UNPACK_F32X2(lo, hi, acc2[u][c]);
            vlo[c] = __uint_as_float(lo);
            vhi[c] = __uint_as_float(hi);
        }
        float mlo = vlo[0], mhi = vhi[0];
        #pragma unroll
        for (int c = 1; c < 8; c++) { mlo = fmaxf(mlo, vlo[c]); mhi = fmaxf(mhi, vhi[c]); }
        #pragma unroll
        for (int s = 1; s < 16; s <<= 1) {
            mlo = fmaxf(mlo, __shfl_xor_sync(0xffffffffu, mlo, s));
            mhi = fmaxf(mhi, __shfl_xor_sync(0xffffffffu, mhi, s));
        }
        float slo = 0.f, shi = 0.f;
        #pragma unroll
        for (int c = 0; c < 8; c++) {
            vlo[c] = __expf(vlo[c] - mlo); slo += vlo[c];
            vhi[c] = __expf(vhi[c] - mhi); shi += vhi[c];
        }
        #pragma unroll
        for (int s = 1; s < 16; s <<= 1) {
            slo += __shfl_xor_sync(0xffffffffu, slo, s);
            shi += __shfl_xor_sync(0xffffffffu, shi, s);
        }
        float ilo = 1.f / slo, ihi = 1.f / shi;
        #pragma unroll
        for (int c = 0; c < 8; c++) {
            unsigned lo = __float_as_uint(vlo[c] * ilo);
            unsigned hi = __float_as_uint(vhi[c] * ihi);
            PACK_F32X2(acc2[u][c], lo, hi);
        }
        if (tx == 0) {
            g_z[(size_t)seg * NTOK + qidx[R0 + 2 * u]]     = __logf(slo) + mlo;
            g_z[(size_t)seg * NTOK + qidx[R0 + 2 * u + 1]] = __logf(shi) + mhi;
        }
    }

    int s = tid & 63;
    int dg = tid >> 6;
    ull oap[3];
    #pragma unroll
    for (int d = 0; d < 3; d++) oap[d] = 0ULL;

    for (int round = 0; round < 4; round++) {
        __syncthreads();
        #pragma unroll
        for (int cc2 = 0; cc2 < 2; cc2++) {
            int cc = round * 2 + cc2;
            int lc = tx + 16 * cc2;
            *(ull*)&pbuf[lc * 134 + R0]     = acc2[0][cc];
            *(ull*)&pbuf[lc * 134 + R0 + 2] = acc2[1][cc];
        }
        __syncthreads();
        #pragma unroll 4
        for (int c16 = 0; c16 < 32; c16++) {
            ull pp = *(const ull*)&pbuf[c16 * 134 + 2 * s];
            int gcol = round * 32 + c16;
            const float* vv = &vs[gcol * 26 + dg * 3];
            #pragma unroll
            for (int d = 0; d < 3; d++) {
                unsigned vb = __float_as_uint(vv[d]);
                ull vp;
                PACK_F32X2(vp, vb, vb);
                FMA_F32X2(oap[d], pp, vp, oap[d]);
            }
        }
    }
    {
        int n0 = qidx[2 * s], n1 = qidx[2 * s + 1];
        float* o0 = &g_o[((size_t)seg * NTOK + n0) * 24 + dg * 3];
        float* o1 = &g_o[((size_t)seg * NTOK + n1) * 24 + dg * 3];
        #pragma unroll
        for (int d = 0; d < 3; d++) {
            unsigned lo, hi;
            UNPACK_F32X2(lo, hi, oap[d]);
            o0[d] = __uint_as_float(lo);
            o1[d] = __uint_as_float(hi);
        }
    }
}

// ---------- combine ----------
__global__ void __launch_bounds__(512) k_combine(
    const float* __restrict__ x, const float* __restrict__ Wo, const float* __restrict__ bo,
    const float* __restrict__ g2, const float* __restrict__ b2v,
    const float* __restrict__ W1, const float* __restrict__ b1v,
    const float* __restrict__ W2, const float* __restrict__ b2f,
    float* __restrict__ out) {
    __shared__ float Wo_s[4608];
    __shared__ float outs[16][192];
    __shared__ float wsm[16][24];
    __shared__ float hsm[16][24];
    __shared__ float fsm[16][24];
    int warp = threadIdx.x >> 5, lane = threadIdx.x & 31;
    int row = blockIdx.x * 16 + warp;

    for (int i = threadIdx.x; i < 4608; i += 512) Wo_s[i] = Wo[i];
    __syncthreads();

    if (lane < 8) {
        int h = lane;
        float z0 = g_z[(size_t)h * NTOK + row];
        float z1 = g_z[(size_t)(8 + h) * NTOK + row];
        float z2 = g_z[(size_t)(16 + h) * NTOK + row];
        float m = fmaxf(z0, fmaxf(z1, z2));
        float e0 = __expf(z0 - m), e1 = __expf(z1 - m), e2 = __expf(z2 - m);
        float inv = 1.f / (e0 + e1 + e2);
        wsm[warp][h * 3 + 0] = e0 * inv;
        wsm[warp][h * 3 + 1] = e1 * inv;
        wsm[warp][h * 3 + 2] = e2 * inv;
    }
    __syncwarp();
    #pragma unroll
    for (int u = 0; u < 6; u++) {
        int j = lane * 6 + u;
        int h = j / 24, d = j - h * 24;
        float a = 0.f;
        #pragma unroll
        for (int r = 0; r < 3; r++)
            a = fmaf(wsm[warp][h * 3 + r], g_o[((size_t)(r * 8 + h) * NTOK + row) * 24 + d], a);
        outs[warp][j] = a;
    }
    __syncwarp();
    float xv = 0.f;
    if (lane < 24) {
        float a = bo[lane];
        #pragma unroll 4
        for (int j = 0; j < 192; j++) a = fmaf(outs[warp][j], Wo_s[j * 24 + lane], a);
        xv = x[(size_t)row * 24 + lane] + a;
    }
    float s = (lane < 24) ? xv : 0.f;
    #pragma unroll
    for (int t = 16; t > 0; t >>= 1) s += __shfl_xor_sync(0xffffffffu, s, t);
    float mu = s * (1.f / 24.f);
    float dv = (lane < 24) ? (xv - mu) : 0.f;
    float v2 = dv * dv;
    #pragma unroll
    for (int t = 16; t > 0; t >>= 1) v2 += __shfl_xor_sync(0xffffffffu, v2, t);
    float inv = rsqrtf(v2 * (1.f / 24.f) + 1e-5f);
    if (lane < 24) hsm[warp][lane] = dv * inv * g2[lane] + b2v[lane];
    __syncwarp();
    if (lane < 24) {
        float f = b1v[lane];
        #pragma unroll
        for (int j = 0; j < 24; j++) f = fmaf(hsm[warp][j], W1[j * 24 + lane], f);
        fsm[warp][lane] = fmaxf(f, 0.f);
    }
    __syncwarp();
    if (lane < 24) {
        float f = b2f[lane];
        #pragma unroll
        for (int j = 0; j < 24; j++) f = fmaf(fsm[warp][j], W2[j * 24 + lane], f);
        out[(size_t)row * 24 + lane] = xv + f;
    }
}

extern "C" void kernel_launch(void* const* d_in, const int* in_sizes, int n_in,
                              void* d_out, int out_size) {
    const float* x      = (const float*)d_in[0];
    const float* coords = (const float*)d_in[1];
    const float* n1g    = (const float*)d_in[2];
    const float* n1b    = (const float*)d_in[3];
    const float* Wq     = (const float*)d_in[4];
    const float* Wk     = (const float*)d_in[5];
    const float* Wv     = (const float*)d_in[6];
    const float* wrpe   = (const float*)d_in[7];
    const float* Wo     = (const float*)d_in[8];
    const float* bo     = (const float*)d_in[9];
    const float* n2g    = (const float*)d_in[10];
    const float* n2b    = (const float*)d_in[11];
    const float* W1     = (const float*)d_in[12];
    const float* b1     = (const float*)d_in[13];
    const float* W2     = (const float*)d_in[14];
    const float* b2     = (const float*)d_in[15];
    const float* alphas = (const float*)d_in[16];
    float* out = (float*)d_out;

    cudaFuncSetAttribute(k_fused, cudaFuncAttributeMaxDynamicSharedMemorySize,
                         FUSED_SMEM_BYTES);

    k_fused<<<NTOK / 64, 576, FUSED_SMEM_BYTES>>>(x, n1g, n1b, Wq, Wk, Wv,
                                                  coords, alphas, wrpe);

    k_presort<<<NSEG * 8, 512>>>();
    // stage k=8192
    k_gmid<<<768, 256>>>(8192);
    k_finish<<<NSEG * 16, 256>>>(8192);
    // stage k=16384
    k_gtop<<<768, 256>>>(16384);
    k_gmid<<<768, 256>>>(16384);
    k_finish<<<NSEG * 16, 256>>>(16384);
    // stage k=32768
    k_gtop<<<768, 256>>>(32768);
    k_gmid<<<768, 256>>>(32768);
    k_finish<<<NSEG * 16, 256>>>(32768);

    dim3 ag(NTOK / 128, NH, 3);
    k_attn<<<ag, 512>>>();
    k_combine<<<NTOK / 16, 512>>>(x, Wo, bo, n2g, n2b, W1, b1, W2, b2, out);
}